// round 9
// baseline (speedup 1.0000x reference)
#include <cuda_runtime.h>
#include <cuda_bf16.h>
#include <cuda_fp8.h>
#include <cstdint>
#include <cstddef>

// ===========================================================================
// DaConA on GB300 (sm_103 PTX target).
// Transfer GEMM (K=960, 276 GF): fp8 e4m3 mma.m16n8k32, inputs scaled x32.
// MLP GEMMs: bf16 mma.m16n8k16.  Both: BM=BN=128, 8 warps 2x4, warp 64x32,
// 3-stage cp.async, ldmatrix w/ hoisted swizzle addressing (R8 winner).
// pred = MLP(concat(u_indep[r], i_indep[c], (Wt@u[r]+bt)*(Wt@i[c]+bt))) + 3.5
// ===========================================================================

#define NB      131072
#define NUSERS  100000
#define NITEMS  50000
#define NEMB    150000          // users then items
#define DIMC    960
#define KPAD    1024            // fp8 K padded with zeros
#define DIMS    32

// fp8 operands (padded to KPAD, zero-filled tail)
__device__ uint8_t g_E8[(size_t)NEMB * KPAD];      // rows: users, then items
__device__ uint8_t g_W8[(size_t)DIMC * KPAD];      // Wt fp8
// bf16 buffers
__device__ __nv_bfloat16 g_T [(size_t)NEMB * DIMC]; // TU rows 0.., TI at +NUSERS
__device__ __nv_bfloat16 g_W1b[512 * 1024];
__device__ __nv_bfloat16 g_W2b[256 * 512];
__device__ __nv_bfloat16 g_W3b[128 * 256];
__device__ __nv_bfloat16 g_F0[(size_t)NB * 1024];
__device__ __nv_bfloat16 g_F1[(size_t)NB * 512];
__device__ __nv_bfloat16 g_F2[(size_t)NB * 256];

__device__ __forceinline__ uint32_t smem_u32(const void* p) {
    uint32_t a;
    asm("{ .reg .u64 t; cvta.to.shared.u64 t, %1; cvt.u32.u64 %0, t; }" : "=r"(a) : "l"(p));
    return a;
}
#define SWZ128(o) ((o) ^ (((o) >> 3) & 0x70))

__device__ __forceinline__ void cp16(uint32_t dst, const void* src, uint32_t sz) {
    asm volatile("cp.async.cg.shared.global [%0], [%1], 16, %2;" :: "r"(dst), "l"(src), "r"(sz));
}
__device__ __forceinline__ void ldsm4(uint32_t* r, uint32_t addr) {
    asm volatile("ldmatrix.sync.aligned.m8n8.x4.shared.b16 {%0,%1,%2,%3}, [%4];"
                 : "=r"(r[0]), "=r"(r[1]), "=r"(r[2]), "=r"(r[3]) : "r"(addr));
}
__device__ __forceinline__ void mma16(float* d, const uint32_t* a, const uint32_t* b) {
    asm volatile("mma.sync.aligned.m16n8k16.row.col.f32.bf16.bf16.f32 "
                 "{%0,%1,%2,%3}, {%4,%5,%6,%7}, {%8,%9}, {%0,%1,%2,%3};"
                 : "+f"(d[0]), "+f"(d[1]), "+f"(d[2]), "+f"(d[3])
                 : "r"(a[0]), "r"(a[1]), "r"(a[2]), "r"(a[3]), "r"(b[0]), "r"(b[1]));
}
__device__ __forceinline__ void mma32f8(float* d, const uint32_t* a, const uint32_t* b) {
    asm volatile("mma.sync.aligned.m16n8k32.row.col.f32.e4m3.e4m3.f32 "
                 "{%0,%1,%2,%3}, {%4,%5,%6,%7}, {%8,%9}, {%0,%1,%2,%3};"
                 : "+f"(d[0]), "+f"(d[1]), "+f"(d[2]), "+f"(d[3])
                 : "r"(a[0]), "r"(a[1]), "r"(a[2]), "r"(a[3]), "r"(b[0]), "r"(b[1]));
}

// ---------------------------------------------------------------------------
// fp8 e4m3 transfer GEMM: T[m][n] = (1/1024)*sum_k E8[m][k]*W8[n][k] + bt[n]
// K = KPAD (zero-padded), BK=128 fp8 per 128B SW128 row, 8 chunks.
// Output bf16, row stride DIMC=960.
// ---------------------------------------------------------------------------
__global__ __launch_bounds__(256) void gemm_f8(
    const uint8_t* __restrict__ A, const uint8_t* __restrict__ Bw,
    const float* __restrict__ bias, __nv_bfloat16* __restrict__ C,
    int M, int N)
{
    extern __shared__ char smem[];
    const uint32_t base = smem_u32(smem);
    const int t = threadIdx.x;
    const int wid = t >> 5, lane = t & 31;
    const int wm = wid >> 2, wn = wid & 3;
    const int g = lane >> 2, q = lane & 3;

    constexpr int TILE = 16384;
    constexpr int SB   = 2 * TILE;
    const int bm = blockIdx.y * 128;
    const int bn = blockIdx.x * 128;

    float* biass = (float*)(smem);
    const uint32_t tiles = (base + 3072 + 1023) & ~1023u;

    for (int j = t; j < 128; j += 256) {
        int gn = bn + j;
        biass[j] = (gn < N) ? bias[gn] : 0.f;
    }

    const int seg = t & 7;
    const int rb  = t >> 3;

    auto load_chunk = [&](int c, int s) {
        const uint32_t at = tiles + s * SB;
        const uint32_t bt_ = at + TILE;
#pragma unroll
        for (int rr = 0; rr < 4; rr++) {
            int row = rb + rr * 32;
            int gr  = bm + row;
            int ok  = gr < M;
            const uint8_t* src = A + (size_t)(ok ? gr : 0) * KPAD + c * 128 + seg * 16;
            cp16(at + SWZ128(row * 128 + seg * 16), src, ok ? 16u : 0u);
        }
#pragma unroll
        for (int rr = 0; rr < 4; rr++) {
            int row = rb + rr * 32;
            int gn  = bn + row;
            int ok  = gn < N;
            const uint8_t* src = Bw + (size_t)(ok ? gn : 0) * KPAD + c * 128 + seg * 16;
            cp16(bt_ + SWZ128(row * 128 + seg * 16), src, ok ? 16u : 0u);
        }
        asm volatile("cp.async.commit_group;" ::: "memory");
    };

    float acc[4][4][4];
#pragma unroll
    for (int i = 0; i < 4; i++)
#pragma unroll
        for (int j = 0; j < 4; j++)
#pragma unroll
            for (int v = 0; v < 4; v++) acc[i][j][v] = 0.f;

    // hoisted ldmatrix addressing (byte-identical to bf16 scheme)
    const int arow = lane & 15;
    const int aoff = (lane >> 4) * 16;
    const int axor = (arow & 7) << 4;
    const int bm8  = lane >> 3;
    const int brow = ((bm8 >> 1) << 3) + (lane & 7);
    const int boff = (bm8 & 1) * 16;
    const int bxor = (lane & 7) << 4;
    uint32_t off_a[4], off_b[4];
#pragma unroll
    for (int ks = 0; ks < 4; ks++) {
        off_a[ks] = (uint32_t)((wm * 64 + arow) * 128 + ((ks * 32 + aoff) ^ axor));
        off_b[ks] = (uint32_t)((wn * 32 + brow) * 128 + ((ks * 32 + boff) ^ bxor)) + TILE;
    }

    const int NKc = KPAD >> 7;          // 8 chunks of 128 fp8
    load_chunk(0, 0);
    load_chunk(1, 1);

    for (int i = 0; i < NKc; i++) {
        const int s = i - (i / 3) * 3;
        if (i + 1 < NKc) asm volatile("cp.async.wait_group 1;" ::: "memory");
        else             asm volatile("cp.async.wait_group 0;" ::: "memory");
        __syncthreads();
        if (i + 2 < NKc) {
            int s2 = i + 2; s2 -= (s2 / 3) * 3;
            load_chunk(i + 2, s2);
        }

        const uint32_t st = tiles + s * SB;
#pragma unroll
        for (int ks = 0; ks < 4; ks++) {        // 4 x k32 per 128B chunk
            uint32_t af[4][4], bf[4][2];
            const uint32_t ab = st + off_a[ks];
            const uint32_t bb = st + off_b[ks];
#pragma unroll
            for (int mt = 0; mt < 4; mt++)
                ldsm4(af[mt], ab + mt * 2048);
#pragma unroll
            for (int np = 0; np < 2; np++) {
                uint32_t r[4];
                ldsm4(r, bb + np * 2048);
                bf[2 * np][0] = r[0]; bf[2 * np][1] = r[1];
                bf[2 * np + 1][0] = r[2]; bf[2 * np + 1][1] = r[3];
            }
#pragma unroll
            for (int mt = 0; mt < 4; mt++)
#pragma unroll
                for (int nt = 0; nt < 4; nt++)
                    mma32f8(acc[mt][nt], af[mt], bf[nt]);
        }
    }
    __syncthreads();

    const float inv = 1.0f / 1024.0f;   // (1/32)^2 input scales
#pragma unroll
    for (int mt = 0; mt < 4; mt++) {
        const int r0 = bm + wm * 64 + mt * 16 + g;
#pragma unroll
        for (int nt = 0; nt < 4; nt++) {
            const int jc = wn * 32 + nt * 8 + 2 * q;
            const int gn = bn + jc;
            if (gn >= N) continue;
            const float bx = biass[jc], by = biass[jc + 1];
            float x0 = acc[mt][nt][0] * inv + bx, x1 = acc[mt][nt][1] * inv + by;
            float x2 = acc[mt][nt][2] * inv + bx, x3 = acc[mt][nt][3] * inv + by;
            if (r0 < M)
                *(__nv_bfloat162*)(C + (size_t)r0 * DIMC + gn) =
                    __nv_bfloat162(__float2bfloat16(x0), __float2bfloat16(x1));
            if (r0 + 8 < M)
                *(__nv_bfloat162*)(C + (size_t)(r0 + 8) * DIMC + gn) =
                    __nv_bfloat162(__float2bfloat16(x2), __float2bfloat16(x3));
        }
    }
}

// ---------------------------------------------------------------------------
// bf16 mma.sync NT GEMM (R8 winner): BM=BN=128, 3-stage, ldmatrix hoisted.
// FINAL: fuse out[b] = tanh(row) . Wr + br + 3.5 (requires N == 128).
// ---------------------------------------------------------------------------
template<bool TANH, bool OUT_BF16, bool FINAL>
__global__ __launch_bounds__(256) void gemm_bf(
    const __nv_bfloat16* __restrict__ A, const __nv_bfloat16* __restrict__ Bw,
    const float* __restrict__ bias, void* __restrict__ Cv,
    const float* __restrict__ Wr, const float* __restrict__ brp,
    int M, int N, int K)
{
    extern __shared__ char smem[];
    const uint32_t base = smem_u32(smem);
    const int t = threadIdx.x;
    const int wid = t >> 5, lane = t & 31;
    const int wm = wid >> 2, wn = wid & 3;
    const int g = lane >> 2, q = lane & 3;

    constexpr int TILE = 16384;
    constexpr int SB   = 2 * TILE;
    const int bm = blockIdx.y * 128;
    const int bn = blockIdx.x * 128;

    float* biass = (float*)(smem);
    float* wrs   = (float*)(smem + 512);
    float* part  = (float*)(smem + 1024);
    const uint32_t tiles = (base + 3072 + 1023) & ~1023u;

    for (int j = t; j < 128; j += 256) {
        int gn = bn + j;
        biass[j] = (gn < N) ? bias[gn] : 0.f;
        if (FINAL) wrs[j] = Wr[j];
    }

    const int seg = t & 7;
    const int rb  = t >> 3;

    auto load_chunk = [&](int c, int s) {
        const uint32_t at = tiles + s * SB;
        const uint32_t bt_ = at + TILE;
#pragma unroll
        for (int rr = 0; rr < 4; rr++) {
            int row = rb + rr * 32;
            int gr  = bm + row;
            int ok  = gr < M;
            const __nv_bfloat16* src = A + (size_t)(ok ? gr : 0) * K + c * 64 + seg * 8;
            cp16(at + SWZ128(row * 128 + seg * 16), src, ok ? 16u : 0u);
        }
#pragma unroll
        for (int rr = 0; rr < 4; rr++) {
            int row = rb + rr * 32;
            int gn  = bn + row;
            int ok  = gn < N;
            const __nv_bfloat16* src = Bw + (size_t)(ok ? gn : 0) * K + c * 64 + seg * 8;
            cp16(bt_ + SWZ128(row * 128 + seg * 16), src, ok ? 16u : 0u);
        }
        asm volatile("cp.async.commit_group;" ::: "memory");
    };

    float acc[4][4][4];
#pragma unroll
    for (int i = 0; i < 4; i++)
#pragma unroll
        for (int j = 0; j < 4; j++)
#pragma unroll
            for (int v = 0; v < 4; v++) acc[i][j][v] = 0.f;

    const int arow = lane & 15;
    const int aoff = (lane >> 4) * 16;
    const int axor = (arow & 7) << 4;
    const int bm8  = lane >> 3;
    const int brow = ((bm8 >> 1) << 3) + (lane & 7);
    const int boff = (bm8 & 1) * 16;
    const int bxor = (lane & 7) << 4;
    uint32_t off_a[4], off_b[4];
#pragma unroll
    for (int ks = 0; ks < 4; ks++) {
        off_a[ks] = (uint32_t)((wm * 64 + arow) * 128 + ((ks * 32 + aoff) ^ axor));
        off_b[ks] = (uint32_t)((wn * 32 + brow) * 128 + ((ks * 32 + boff) ^ bxor)) + TILE;
    }

    const int NKc = K >> 6;
    load_chunk(0, 0);
    load_chunk(1, 1);

    for (int i = 0; i < NKc; i++) {
        const int s = i - (i / 3) * 3;
        if (i + 1 < NKc) asm volatile("cp.async.wait_group 1;" ::: "memory");
        else             asm volatile("cp.async.wait_group 0;" ::: "memory");
        __syncthreads();
        if (i + 2 < NKc) {
            int s2 = i + 2; s2 -= (s2 / 3) * 3;
            load_chunk(i + 2, s2);
        }

        const uint32_t st = tiles + s * SB;
#pragma unroll
        for (int ks = 0; ks < 4; ks++) {
            uint32_t af[4][4], bf[4][2];
            const uint32_t ab = st + off_a[ks];
            const uint32_t bb = st + off_b[ks];
#pragma unroll
            for (int mt = 0; mt < 4; mt++)
                ldsm4(af[mt], ab + mt * 2048);
#pragma unroll
            for (int np = 0; np < 2; np++) {
                uint32_t r[4];
                ldsm4(r, bb + np * 2048);
                bf[2 * np][0] = r[0]; bf[2 * np][1] = r[1];
                bf[2 * np + 1][0] = r[2]; bf[2 * np + 1][1] = r[3];
            }
#pragma unroll
            for (int mt = 0; mt < 4; mt++)
#pragma unroll
                for (int nt = 0; nt < 4; nt++)
                    mma16(acc[mt][nt], af[mt], bf[nt]);
        }
    }
    __syncthreads();

    if (FINAL) {
#pragma unroll
        for (int mt = 0; mt < 4; mt++) {
            float p0 = 0.f, p1 = 0.f;
#pragma unroll
            for (int nt = 0; nt < 4; nt++) {
                const int jc = wn * 32 + nt * 8 + 2 * q;
                const float bx = biass[jc], by = biass[jc + 1];
                const float wx = wrs[jc],  wy = wrs[jc + 1];
                p0 += tanhf(acc[mt][nt][0] + bx) * wx + tanhf(acc[mt][nt][1] + by) * wy;
                p1 += tanhf(acc[mt][nt][2] + bx) * wx + tanhf(acc[mt][nt][3] + by) * wy;
            }
            p0 += __shfl_xor_sync(0xFFFFFFFFu, p0, 1);
            p0 += __shfl_xor_sync(0xFFFFFFFFu, p0, 2);
            p1 += __shfl_xor_sync(0xFFFFFFFFu, p1, 1);
            p1 += __shfl_xor_sync(0xFFFFFFFFu, p1, 2);
            if (q == 0) {
                part[(wm * 64 + mt * 16 + g) * 4 + wn]     = p0;
                part[(wm * 64 + mt * 16 + g + 8) * 4 + wn] = p1;
            }
        }
        __syncthreads();
        if (t < 128) {
            float s = part[t * 4] + part[t * 4 + 1] + part[t * 4 + 2] + part[t * 4 + 3];
            if (bm + t < M) ((float*)Cv)[bm + t] = s + brp[0] + 3.5f;
        }
        return;
    }

#pragma unroll
    for (int mt = 0; mt < 4; mt++) {
        const int r0 = bm + wm * 64 + mt * 16 + g;
#pragma unroll
        for (int nt = 0; nt < 4; nt++) {
            const int jc = wn * 32 + nt * 8 + 2 * q;
            const int gn = bn + jc;
            if (gn >= N) continue;
            const float bx = biass[jc], by = biass[jc + 1];
            float x0 = acc[mt][nt][0] + bx, x1 = acc[mt][nt][1] + by;
            float x2 = acc[mt][nt][2] + bx, x3 = acc[mt][nt][3] + by;
            if (TANH) { x0 = tanhf(x0); x1 = tanhf(x1); x2 = tanhf(x2); x3 = tanhf(x3); }
            if (OUT_BF16) {
                __nv_bfloat16* C = (__nv_bfloat16*)Cv;
                if (r0 < M)
                    *(__nv_bfloat162*)(C + (size_t)r0 * N + gn) =
                        __nv_bfloat162(__float2bfloat16(x0), __float2bfloat16(x1));
                if (r0 + 8 < M)
                    *(__nv_bfloat162*)(C + (size_t)(r0 + 8) * N + gn) =
                        __nv_bfloat162(__float2bfloat16(x2), __float2bfloat16(x3));
            } else {
                float* C = (float*)Cv;
                if (r0 < M)     *(float2*)(C + (size_t)r0 * N + gn)       = make_float2(x0, x1);
                if (r0 + 8 < M) *(float2*)(C + (size_t)(r0 + 8) * N + gn) = make_float2(x2, x3);
            }
        }
    }
}

// ---------------------------------------------------------------------------
// fp8 conversion: one block per 960-elem row -> 1024-byte padded fp8 row.
// blocks [0, NEMB): embeddings (users then items); [NEMB, NEMB+960): Wt.
// ---------------------------------------------------------------------------
__global__ __launch_bounds__(256) void conv_fp8(
    const float* __restrict__ user_inter, const float* __restrict__ item_inter,
    const float* __restrict__ Wt,
    uint8_t* __restrict__ E8, uint8_t* __restrict__ W8)
{
    const int b = blockIdx.x;
    const int tid = threadIdx.x;
    const float* src;
    uint8_t* dst;
    if (b < NUSERS)       { src = user_inter + (size_t)b * DIMC;             dst = E8 + (size_t)b * KPAD; }
    else if (b < NEMB)    { src = item_inter + (size_t)(b - NUSERS) * DIMC;  dst = E8 + (size_t)b * KPAD; }
    else                  { src = Wt + (size_t)(b - NEMB) * DIMC;            dst = W8 + (size_t)(b - NEMB) * KPAD; }

    uint32_t w = 0;
    if (tid < 240) {
        float4 v = *(const float4*)(src + tid * 4);
        __nv_fp8x2_storage_t lo = __nv_cvt_float2_to_fp8x2(
            make_float2(v.x * 32.f, v.y * 32.f), __NV_SATFINITE, __NV_E4M3);
        __nv_fp8x2_storage_t hi = __nv_cvt_float2_to_fp8x2(
            make_float2(v.z * 32.f, v.w * 32.f), __NV_SATFINITE, __NV_E4M3);
        w = (uint32_t)lo | ((uint32_t)hi << 16);
    }
    ((uint32_t*)dst)[tid] = w;
}

// ---------------------------------------------------------------------------
// fp32 -> bf16 weights: W1(512 blks) | W2(128) | W3(32), 1024 elems/block
// ---------------------------------------------------------------------------
__device__ __forceinline__ void conv_blk(const float* src, __nv_bfloat16* dst, size_t blk) {
    const size_t i = blk * 1024 + threadIdx.x * 4;
    float4 v = *(const float4*)(src + i);
    *(__nv_bfloat162*)(dst + i)     = __nv_bfloat162(__float2bfloat16(v.x), __float2bfloat16(v.y));
    *(__nv_bfloat162*)(dst + i + 2) = __nv_bfloat162(__float2bfloat16(v.z), __float2bfloat16(v.w));
}

__global__ __launch_bounds__(256) void conv_wbf(
    const float* __restrict__ W1, const float* __restrict__ W2,
    const float* __restrict__ W3,
    __nv_bfloat16* __restrict__ W1b, __nv_bfloat16* __restrict__ W2b,
    __nv_bfloat16* __restrict__ W3b)
{
    const int b = blockIdx.x;
    if      (b < 512) conv_blk(W1, W1b, b);
    else if (b < 640) conv_blk(W2, W2b, b - 512);
    else              conv_blk(W3, W3b, b - 640);
}

// ---------------------------------------------------------------------------
// Gather + elementwise product + concat into F0[B, 1024] (bf16)
// ---------------------------------------------------------------------------
__global__ __launch_bounds__(256) void build_factor(
    const int* __restrict__ rows, const int* __restrict__ cols,
    const float* __restrict__ uix, const float* __restrict__ iix,
    const __nv_bfloat16* __restrict__ T, __nv_bfloat16* __restrict__ F0)
{
    const int b = blockIdx.x;
    const int r = rows[b];
    const int c = cols[b];
    const int f = threadIdx.x * 4;

    float4 v;
    if (f < 32) {
        v = *(const float4*)(uix + (size_t)r * DIMS + f);
    } else if (f < 64) {
        v = *(const float4*)(iix + (size_t)c * DIMS + (f - 32));
    } else {
        const __nv_bfloat162* a  = (const __nv_bfloat162*)(T + (size_t)r * DIMC + (f - 64));
        const __nv_bfloat162* bb = (const __nv_bfloat162*)(T + (size_t)(NUSERS + c) * DIMC + (f - 64));
        float2 a0 = __bfloat1622float2(a[0]),  a1 = __bfloat1622float2(a[1]);
        float2 b0 = __bfloat1622float2(bb[0]), b1 = __bfloat1622float2(bb[1]);
        v = make_float4(a0.x * b0.x, a0.y * b0.y, a1.x * b1.x, a1.y * b1.y);
    }
    __nv_bfloat16* o = F0 + (size_t)b * 1024 + f;
    *(__nv_bfloat162*)(o)     = __nv_bfloat162(__float2bfloat16(v.x), __float2bfloat16(v.y));
    *(__nv_bfloat162*)(o + 2) = __nv_bfloat162(__float2bfloat16(v.z), __float2bfloat16(v.w));
}

// ---------------------------------------------------------------------------
extern "C" void kernel_launch(void* const* d_in, const int* in_sizes, int n_in,
                              void* d_out, int out_size)
{
    const int*   rows       = (const int*)d_in[0];
    const int*   cols       = (const int*)d_in[1];
    const float* user_inter = (const float*)d_in[2];
    const float* item_inter = (const float*)d_in[3];
    const float* uix        = (const float*)d_in[4];
    const float* iix        = (const float*)d_in[5];
    const float* Wt         = (const float*)d_in[6];
    const float* bt         = (const float*)d_in[7];
    const float* W1         = (const float*)d_in[8];
    const float* b1         = (const float*)d_in[9];
    const float* W2         = (const float*)d_in[10];
    const float* b2         = (const float*)d_in[11];
    const float* W3         = (const float*)d_in[12];
    const float* b3         = (const float*)d_in[13];
    const float* Wr         = (const float*)d_in[14];
    const float* br         = (const float*)d_in[15];
    float*       out        = (float*)d_out;

    uint8_t *E8, *W8;
    __nv_bfloat16 *T, *W1b, *W2b, *W3b, *F0, *F1, *F2;
    cudaGetSymbolAddress((void**)&E8, g_E8);
    cudaGetSymbolAddress((void**)&W8, g_W8);
    cudaGetSymbolAddress((void**)&T,  g_T);
    cudaGetSymbolAddress((void**)&W1b, g_W1b);
    cudaGetSymbolAddress((void**)&W2b, g_W2b);
    cudaGetSymbolAddress((void**)&W3b, g_W3b);
    cudaGetSymbolAddress((void**)&F0, g_F0);
    cudaGetSymbolAddress((void**)&F1, g_F1);
    cudaGetSymbolAddress((void**)&F2, g_F2);

    const int SZ = 3072 + 1024 + 3 * 32768;   // 102400
    cudaFuncSetAttribute(gemm_f8, cudaFuncAttributeMaxDynamicSharedMemorySize, SZ);
    cudaFuncSetAttribute(gemm_bf<true, true, false>,  cudaFuncAttributeMaxDynamicSharedMemorySize, SZ);
    cudaFuncSetAttribute(gemm_bf<true, false, true>,  cudaFuncAttributeMaxDynamicSharedMemorySize, SZ);

    const dim3 blk(256);

    // 0) conversions: embeddings+Wt -> fp8 (scaled x32), MLP weights -> bf16
    conv_fp8<<<NEMB + DIMC, blk>>>(user_inter, item_inter, Wt, E8, W8);
    conv_wbf<<<672, blk>>>(W1, W2, W3, W1b, W2b, W3b);

    // 1) Combined transfer transform: T[150000, 960] in ONE fp8 GEMM
    gemm_f8<<<dim3(8, (NEMB + 127) / 128), blk, SZ>>>(E8, W8, bt, T, NEMB, DIMC);

    // 2) Gather + elementwise product + concat
    build_factor<<<NB, blk>>>(rows, cols, uix, iix, T, F0);

    // 3) MLP layers (bf16); last fuses Wr-dot + br + 3.5
    gemm_bf<true, true, false><<<dim3(4, NB / 128), blk, SZ>>>(
        F0, W1b, b1, F1, nullptr, nullptr, NB, 512, 1024);
    gemm_bf<true, true, false><<<dim3(2, NB / 128), blk, SZ>>>(
        F1, W2b, b2, F2, nullptr, nullptr, NB, 256, 512);
    gemm_bf<true, false, true><<<dim3(1, NB / 128), blk, SZ>>>(
        F2, W3b, b3, out, Wr, br, NB, 128, 256);
}

// round 10
// speedup vs baseline: 1.3061x; 1.3061x over previous
#include <cuda_runtime.h>
#include <cuda_bf16.h>
#include <cstdint>
#include <cstddef>

// ===========================================================================
// DaConA on GB300 (sm_103 PTX target: mma.sync bf16 HMMA k16 + ldmatrix with
// hoisted swizzle addressing -- R8 winner mainloop).
// New in R10: transfer GEMM computes ONLY entity rows referenced by the batch
// (mark -> compact list -> gather/scatter GEMM), ~80% of rows.
// pred = MLP(concat(u_indep[r], i_indep[c], (Wt@u[r]+bt)*(Wt@i[c]+bt))) + 3.5
// ===========================================================================

#define NB      131072
#define NUSERS  100000
#define NITEMS  50000
#define NEMB    150000          // users then items
#define DIMC    960
#define DIMS    32

__device__ __nv_bfloat16 g_Eb[(size_t)NEMB * DIMC];   // bf16 embeddings (u|i)
__device__ __nv_bfloat16 g_Wtb[(size_t)DIMC * DIMC];
__device__ __nv_bfloat16 g_T [(size_t)NEMB * DIMC];   // transfer outputs (u|i)
__device__ __nv_bfloat16 g_W1b[512 * 1024];
__device__ __nv_bfloat16 g_W2b[256 * 512];
__device__ __nv_bfloat16 g_W3b[128 * 256];
__device__ __nv_bfloat16 g_F0[(size_t)NB * 1024];
__device__ __nv_bfloat16 g_F1[(size_t)NB * 512];
__device__ __nv_bfloat16 g_F2[(size_t)NB * 256];
__device__ unsigned char g_used[NEMB];
__device__ int g_list[NEMB];
__device__ int g_cnt;

__device__ __forceinline__ uint32_t smem_u32(const void* p) {
    uint32_t a;
    asm("{ .reg .u64 t; cvta.to.shared.u64 t, %1; cvt.u32.u64 %0, t; }" : "=r"(a) : "l"(p));
    return a;
}
#define SWZ128(o) ((o) ^ (((o) >> 3) & 0x70))

__device__ __forceinline__ void cp16(uint32_t dst, const void* src, uint32_t sz) {
    asm volatile("cp.async.cg.shared.global [%0], [%1], 16, %2;" :: "r"(dst), "l"(src), "r"(sz));
}
__device__ __forceinline__ void ldsm4(uint32_t* r, uint32_t addr) {
    asm volatile("ldmatrix.sync.aligned.m8n8.x4.shared.b16 {%0,%1,%2,%3}, [%4];"
                 : "=r"(r[0]), "=r"(r[1]), "=r"(r[2]), "=r"(r[3]) : "r"(addr));
}
__device__ __forceinline__ void mma16(float* d, const uint32_t* a, const uint32_t* b) {
    asm volatile("mma.sync.aligned.m16n8k16.row.col.f32.bf16.bf16.f32 "
                 "{%0,%1,%2,%3}, {%4,%5,%6,%7}, {%8,%9}, {%0,%1,%2,%3};"
                 : "+f"(d[0]), "+f"(d[1]), "+f"(d[2]), "+f"(d[3])
                 : "r"(a[0]), "r"(a[1]), "r"(a[2]), "r"(a[3]), "r"(b[0]), "r"(b[1]));
}

// ---------------------------------------------------------------------------
// Aux: zero bitmap+counter; mark used entities; build compact list.
// List order is atomicAdd-nondeterministic but per-row results are order-
// independent -> output T is deterministic.
// ---------------------------------------------------------------------------
__global__ __launch_bounds__(256) void zero_aux() {
    const int i = blockIdx.x * 256 + threadIdx.x;
    if (i < NEMB / 4) ((uint32_t*)g_used)[i] = 0;
    if (i == 0) { g_cnt = 0; ((uint32_t*)g_used)[NEMB / 4] = 0; }  // 150000 = 37500*4
}
__global__ __launch_bounds__(256) void mark_used(
    const int* __restrict__ rows, const int* __restrict__ cols) {
    const int i = blockIdx.x * 256 + threadIdx.x;
    g_used[rows[i]] = 1;
    g_used[NUSERS + cols[i]] = 1;
}
__global__ __launch_bounds__(256) void build_list() {
    const int e = blockIdx.x * 256 + threadIdx.x;
    if (e < NEMB && g_used[e]) {
        int p = atomicAdd(&g_cnt, 1);
        g_list[p] = e;
    }
}

// ---------------------------------------------------------------------------
// Transfer GEMM over COMPACTED rows:
//   T[list[r]][n] = sum_k Eb[list[r]][k] * Wtb[n][k] + bt[n]
// K = N = 960.  BM=BN=128, 3-stage cp.async, ldmatrix hoisted (R8 mainloop).
// ---------------------------------------------------------------------------
__global__ __launch_bounds__(256) void gemm_tr(
    const __nv_bfloat16* __restrict__ Eb, const __nv_bfloat16* __restrict__ Bw,
    const float* __restrict__ bias, __nv_bfloat16* __restrict__ T)
{
    const int cnt = g_cnt;
    const int bm = blockIdx.y * 128;
    if (bm >= cnt) return;
    const int bn = blockIdx.x * 128;

    extern __shared__ char smem[];
    const uint32_t base = smem_u32(smem);
    const int t = threadIdx.x;
    const int wid = t >> 5, lane = t & 31;
    const int wm = wid >> 2, wn = wid & 3;
    const int g = lane >> 2, q = lane & 3;

    constexpr int TILE = 16384;
    constexpr int SB   = 2 * TILE;

    float* biass = (float*)(smem);            // 512 B
    int*   idxs  = (int*)(smem + 1024);       // 512 B
    const uint32_t tiles = (base + 3072 + 1023) & ~1023u;

    for (int j = t; j < 128; j += 256) {
        int gn = bn + j;
        biass[j] = (gn < DIMC) ? bias[gn] : 0.f;
        idxs[j]  = (bm + j < cnt) ? g_list[bm + j] : 0;
    }

    const int seg = t & 7;
    const int rb  = t >> 3;

    // preload this thread's 4 A-row indices
    int aidx[4]; uint32_t aok[4];
#pragma unroll
    for (int rr = 0; rr < 4; rr++) {
        int gr = bm + rb + rr * 32;
        aok[rr]  = (gr < cnt) ? 16u : 0u;
        aidx[rr] = (gr < cnt) ? g_list[gr] : 0;
    }

    auto load_chunk = [&](int c, int s) {
        const uint32_t at = tiles + s * SB;
        const uint32_t bt_ = at + TILE;
#pragma unroll
        for (int rr = 0; rr < 4; rr++) {
            int row = rb + rr * 32;
            const __nv_bfloat16* src = Eb + (size_t)aidx[rr] * DIMC + c * 64 + seg * 8;
            cp16(at + SWZ128(row * 128 + seg * 16), src, aok[rr]);
        }
#pragma unroll
        for (int rr = 0; rr < 4; rr++) {
            int row = rb + rr * 32;
            int gn  = bn + row;
            int ok  = gn < DIMC;
            const __nv_bfloat16* src = Bw + (size_t)(ok ? gn : 0) * DIMC + c * 64 + seg * 8;
            cp16(bt_ + SWZ128(row * 128 + seg * 16), src, ok ? 16u : 0u);
        }
        asm volatile("cp.async.commit_group;" ::: "memory");
    };

    float acc[4][4][4];
#pragma unroll
    for (int i = 0; i < 4; i++)
#pragma unroll
        for (int j = 0; j < 4; j++)
#pragma unroll
            for (int v = 0; v < 4; v++) acc[i][j][v] = 0.f;

    const int arow = lane & 15;
    const int aoff = (lane >> 4) * 16;
    const int axor = (arow & 7) << 4;
    const int bm8  = lane >> 3;
    const int brow = ((bm8 >> 1) << 3) + (lane & 7);
    const int boff = (bm8 & 1) * 16;
    const int bxor = (lane & 7) << 4;
    uint32_t off_a[4], off_b[4];
#pragma unroll
    for (int ks = 0; ks < 4; ks++) {
        off_a[ks] = (uint32_t)((wm * 64 + arow) * 128 + ((ks * 32 + aoff) ^ axor));
        off_b[ks] = (uint32_t)((wn * 32 + brow) * 128 + ((ks * 32 + boff) ^ bxor)) + TILE;
    }

    const int NKc = DIMC >> 6;          // 15 chunks
    load_chunk(0, 0);
    load_chunk(1, 1);

    for (int i = 0; i < NKc; i++) {
        const int s = i - (i / 3) * 3;
        if (i + 1 < NKc) asm volatile("cp.async.wait_group 1;" ::: "memory");
        else             asm volatile("cp.async.wait_group 0;" ::: "memory");
        __syncthreads();
        if (i + 2 < NKc) {
            int s2 = i + 2; s2 -= (s2 / 3) * 3;
            load_chunk(i + 2, s2);
        }

        const uint32_t st = tiles + s * SB;
#pragma unroll
        for (int ks = 0; ks < 4; ks++) {
            uint32_t af[4][4], bf[4][2];
            const uint32_t ab = st + off_a[ks];
            const uint32_t bb = st + off_b[ks];
#pragma unroll
            for (int mt = 0; mt < 4; mt++)
                ldsm4(af[mt], ab + mt * 2048);
#pragma unroll
            for (int np = 0; np < 2; np++) {
                uint32_t r[4];
                ldsm4(r, bb + np * 2048);
                bf[2 * np][0] = r[0]; bf[2 * np][1] = r[1];
                bf[2 * np + 1][0] = r[2]; bf[2 * np + 1][1] = r[3];
            }
#pragma unroll
            for (int mt = 0; mt < 4; mt++)
#pragma unroll
                for (int nt = 0; nt < 4; nt++)
                    mma16(acc[mt][nt], af[mt], bf[nt]);
        }
    }
    __syncthreads();

#pragma unroll
    for (int mt = 0; mt < 4; mt++) {
        const int er0 = wm * 64 + mt * 16 + g;
#pragma unroll
        for (int nt = 0; nt < 4; nt++) {
            const int jc = wn * 32 + nt * 8 + 2 * q;
            const int gn = bn + jc;
            if (gn >= DIMC) continue;
            const float bx = biass[jc], by = biass[jc + 1];
            float x0 = acc[mt][nt][0] + bx, x1 = acc[mt][nt][1] + by;
            float x2 = acc[mt][nt][2] + bx, x3 = acc[mt][nt][3] + by;
            if (bm + er0 < cnt)
                *(__nv_bfloat162*)(T + (size_t)idxs[er0] * DIMC + gn) =
                    __nv_bfloat162(__float2bfloat16(x0), __float2bfloat16(x1));
            if (bm + er0 + 8 < cnt)
                *(__nv_bfloat162*)(T + (size_t)idxs[er0 + 8] * DIMC + gn) =
                    __nv_bfloat162(__float2bfloat16(x2), __float2bfloat16(x3));
        }
    }
}

// ---------------------------------------------------------------------------
// bf16 mma.sync NT GEMM (R8 winner): BM=BN=128, 3-stage, ldmatrix hoisted.
// FINAL: fuse out[b] = tanh(row) . Wr + br + 3.5 (requires N == 128).
// ---------------------------------------------------------------------------
template<bool TANH, bool OUT_BF16, bool FINAL>
__global__ __launch_bounds__(256) void gemm_bf(
    const __nv_bfloat16* __restrict__ A, const __nv_bfloat16* __restrict__ Bw,
    const float* __restrict__ bias, void* __restrict__ Cv,
    const float* __restrict__ Wr, const float* __restrict__ brp,
    int M, int N, int K)
{
    extern __shared__ char smem[];
    const uint32_t base = smem_u32(smem);
    const int t = threadIdx.x;
    const int wid = t >> 5, lane = t & 31;
    const int wm = wid >> 2, wn = wid & 3;
    const int g = lane >> 2, q = lane & 3;

    constexpr int TILE = 16384;
    constexpr int SB   = 2 * TILE;
    const int bm = blockIdx.y * 128;
    const int bn = blockIdx.x * 128;

    float* biass = (float*)(smem);
    float* wrs   = (float*)(smem + 512);
    float* part  = (float*)(smem + 1024);
    const uint32_t tiles = (base + 3072 + 1023) & ~1023u;

    for (int j = t; j < 128; j += 256) {
        int gn = bn + j;
        biass[j] = (gn < N) ? bias[gn] : 0.f;
        if (FINAL) wrs[j] = Wr[j];
    }

    const int seg = t & 7;
    const int rb  = t >> 3;

    auto load_chunk = [&](int c, int s) {
        const uint32_t at = tiles + s * SB;
        const uint32_t bt_ = at + TILE;
#pragma unroll
        for (int rr = 0; rr < 4; rr++) {
            int row = rb + rr * 32;
            int gr  = bm + row;
            int ok  = gr < M;
            const __nv_bfloat16* src = A + (size_t)(ok ? gr : 0) * K + c * 64 + seg * 8;
            cp16(at + SWZ128(row * 128 + seg * 16), src, ok ? 16u : 0u);
        }
#pragma unroll
        for (int rr = 0; rr < 4; rr++) {
            int row = rb + rr * 32;
            int gn  = bn + row;
            int ok  = gn < N;
            const __nv_bfloat16* src = Bw + (size_t)(ok ? gn : 0) * K + c * 64 + seg * 8;
            cp16(bt_ + SWZ128(row * 128 + seg * 16), src, ok ? 16u : 0u);
        }
        asm volatile("cp.async.commit_group;" ::: "memory");
    };

    float acc[4][4][4];
#pragma unroll
    for (int i = 0; i < 4; i++)
#pragma unroll
        for (int j = 0; j < 4; j++)
#pragma unroll
            for (int v = 0; v < 4; v++) acc[i][j][v] = 0.f;

    const int arow = lane & 15;
    const int aoff = (lane >> 4) * 16;
    const int axor = (arow & 7) << 4;
    const int bm8  = lane >> 3;
    const int brow = ((bm8 >> 1) << 3) + (lane & 7);
    const int boff = (bm8 & 1) * 16;
    const int bxor = (lane & 7) << 4;
    uint32_t off_a[4], off_b[4];
#pragma unroll
    for (int ks = 0; ks < 4; ks++) {
        off_a[ks] = (uint32_t)((wm * 64 + arow) * 128 + ((ks * 32 + aoff) ^ axor));
        off_b[ks] = (uint32_t)((wn * 32 + brow) * 128 + ((ks * 32 + boff) ^ bxor)) + TILE;
    }

    const int NKc = K >> 6;
    load_chunk(0, 0);
    load_chunk(1, 1);

    for (int i = 0; i < NKc; i++) {
        const int s = i - (i / 3) * 3;
        if (i + 1 < NKc) asm volatile("cp.async.wait_group 1;" ::: "memory");
        else             asm volatile("cp.async.wait_group 0;" ::: "memory");
        __syncthreads();
        if (i + 2 < NKc) {
            int s2 = i + 2; s2 -= (s2 / 3) * 3;
            load_chunk(i + 2, s2);
        }

        const uint32_t st = tiles + s * SB;
#pragma unroll
        for (int ks = 0; ks < 4; ks++) {
            uint32_t af[4][4], bf[4][2];
            const uint32_t ab = st + off_a[ks];
            const uint32_t bb = st + off_b[ks];
#pragma unroll
            for (int mt = 0; mt < 4; mt++)
                ldsm4(af[mt], ab + mt * 2048);
#pragma unroll
            for (int np = 0; np < 2; np++) {
                uint32_t r[4];
                ldsm4(r, bb + np * 2048);
                bf[2 * np][0] = r[0]; bf[2 * np][1] = r[1];
                bf[2 * np + 1][0] = r[2]; bf[2 * np + 1][1] = r[3];
            }
#pragma unroll
            for (int mt = 0; mt < 4; mt++)
#pragma unroll
                for (int nt = 0; nt < 4; nt++)
                    mma16(acc[mt][nt], af[mt], bf[nt]);
        }
    }
    __syncthreads();

    if (FINAL) {
#pragma unroll
        for (int mt = 0; mt < 4; mt++) {
            float p0 = 0.f, p1 = 0.f;
#pragma unroll
            for (int nt = 0; nt < 4; nt++) {
                const int jc = wn * 32 + nt * 8 + 2 * q;
                const float bx = biass[jc], by = biass[jc + 1];
                const float wx = wrs[jc],  wy = wrs[jc + 1];
                p0 += tanhf(acc[mt][nt][0] + bx) * wx + tanhf(acc[mt][nt][1] + by) * wy;
                p1 += tanhf(acc[mt][nt][2] + bx) * wx + tanhf(acc[mt][nt][3] + by) * wy;
            }
            p0 += __shfl_xor_sync(0xFFFFFFFFu, p0, 1);
            p0 += __shfl_xor_sync(0xFFFFFFFFu, p0, 2);
            p1 += __shfl_xor_sync(0xFFFFFFFFu, p1, 1);
            p1 += __shfl_xor_sync(0xFFFFFFFFu, p1, 2);
            if (q == 0) {
                part[(wm * 64 + mt * 16 + g) * 4 + wn]     = p0;
                part[(wm * 64 + mt * 16 + g + 8) * 4 + wn] = p1;
            }
        }
        __syncthreads();
        if (t < 128) {
            float s = part[t * 4] + part[t * 4 + 1] + part[t * 4 + 2] + part[t * 4 + 3];
            if (bm + t < M) ((float*)Cv)[bm + t] = s + brp[0] + 3.5f;
        }
        return;
    }

#pragma unroll
    for (int mt = 0; mt < 4; mt++) {
        const int r0 = bm + wm * 64 + mt * 16 + g;
#pragma unroll
        for (int nt = 0; nt < 4; nt++) {
            const int jc = wn * 32 + nt * 8 + 2 * q;
            const int gn = bn + jc;
            if (gn >= N) continue;
            const float bx = biass[jc], by = biass[jc + 1];
            float x0 = acc[mt][nt][0] + bx, x1 = acc[mt][nt][1] + by;
            float x2 = acc[mt][nt][2] + bx, x3 = acc[mt][nt][3] + by;
            if (TANH) { x0 = tanhf(x0); x1 = tanhf(x1); x2 = tanhf(x2); x3 = tanhf(x3); }
            if (OUT_BF16) {
                __nv_bfloat16* C = (__nv_bfloat16*)Cv;
                if (r0 < M)
                    *(__nv_bfloat162*)(C + (size_t)r0 * N + gn) =
                        __nv_bfloat162(__float2bfloat16(x0), __float2bfloat16(x1));
                if (r0 + 8 < M)
                    *(__nv_bfloat162*)(C + (size_t)(r0 + 8) * N + gn) =
                        __nv_bfloat162(__float2bfloat16(x2), __float2bfloat16(x3));
            } else {
                float* C = (float*)Cv;
                if (r0 < M)     *(float2*)(C + (size_t)r0 * N + gn)       = make_float2(x0, x1);
                if (r0 + 8 < M) *(float2*)(C + (size_t)(r0 + 8) * N + gn) = make_float2(x2, x3);
            }
        }
    }
}

// ---------------------------------------------------------------------------
// fp32 -> bf16 conversions
// ---------------------------------------------------------------------------
__device__ __forceinline__ void conv_blk(const float* src, __nv_bfloat16* dst, size_t blk) {
    const size_t i = blk * 1024 + threadIdx.x * 4;
    float4 v = *(const float4*)(src + i);
    *(__nv_bfloat162*)(dst + i)     = __nv_bfloat162(__float2bfloat16(v.x), __float2bfloat16(v.y));
    *(__nv_bfloat162*)(dst + i + 2) = __nv_bfloat162(__float2bfloat16(v.z), __float2bfloat16(v.w));
}

// users (93750 blks) then items (46875) into combined Eb
__global__ __launch_bounds__(256) void conv_emb(
    const float* __restrict__ user_inter, const float* __restrict__ item_inter,
    __nv_bfloat16* __restrict__ Eb)
{
    const int b = blockIdx.x;
    if (b < 93750) conv_blk(user_inter, Eb, b);
    else           conv_blk(item_inter, Eb + (size_t)NUSERS * DIMC, b - 93750);
}

// Wt(900) | W1(512) | W2(128) | W3(32)
__global__ __launch_bounds__(256) void conv_w(
    const float* __restrict__ Wt, const float* __restrict__ W1,
    const float* __restrict__ W2, const float* __restrict__ W3,
    __nv_bfloat16* __restrict__ Wtb, __nv_bfloat16* __restrict__ W1b,
    __nv_bfloat16* __restrict__ W2b, __nv_bfloat16* __restrict__ W3b)
{
    const int b = blockIdx.x;
    if      (b < 900)  conv_blk(Wt, Wtb, b);
    else if (b < 1412) conv_blk(W1, W1b, b - 900);
    else if (b < 1540) conv_blk(W2, W2b, b - 1412);
    else               conv_blk(W3, W3b, b - 1540);
}

// ---------------------------------------------------------------------------
// Gather + elementwise product + concat into F0[B, 1024] (bf16)
// ---------------------------------------------------------------------------
__global__ __launch_bounds__(256) void build_factor(
    const int* __restrict__ rows, const int* __restrict__ cols,
    const float* __restrict__ uix, const float* __restrict__ iix,
    const __nv_bfloat16* __restrict__ T, __nv_bfloat16* __restrict__ F0)
{
    const int b = blockIdx.x;
    const int r = rows[b];
    const int c = cols[b];
    const int f = threadIdx.x * 4;

    float4 v;
    if (f < 32) {
        v = *(const float4*)(uix + (size_t)r * DIMS + f);
    } else if (f < 64) {
        v = *(const float4*)(iix + (size_t)c * DIMS + (f - 32));
    } else {
        const __nv_bfloat162* a  = (const __nv_bfloat162*)(T + (size_t)r * DIMC + (f - 64));
        const __nv_bfloat162* bb = (const __nv_bfloat162*)(T + (size_t)(NUSERS + c) * DIMC + (f - 64));
        float2 a0 = __bfloat1622float2(a[0]),  a1 = __bfloat1622float2(a[1]);
        float2 b0 = __bfloat1622float2(bb[0]), b1 = __bfloat1622float2(bb[1]);
        v = make_float4(a0.x * b0.x, a0.y * b0.y, a1.x * b1.x, a1.y * b1.y);
    }
    __nv_bfloat16* o = F0 + (size_t)b * 1024 + f;
    *(__nv_bfloat162*)(o)     = __nv_bfloat162(__float2bfloat16(v.x), __float2bfloat16(v.y));
    *(__nv_bfloat162*)(o + 2) = __nv_bfloat162(__float2bfloat16(v.z), __float2bfloat16(v.w));
}

// ---------------------------------------------------------------------------
extern "C" void kernel_launch(void* const* d_in, const int* in_sizes, int n_in,
                              void* d_out, int out_size)
{
    const int*   rows       = (const int*)d_in[0];
    const int*   cols       = (const int*)d_in[1];
    const float* user_inter = (const float*)d_in[2];
    const float* item_inter = (const float*)d_in[3];
    const float* uix        = (const float*)d_in[4];
    const float* iix        = (const float*)d_in[5];
    const float* Wt         = (const float*)d_in[6];
    const float* bt         = (const float*)d_in[7];
    const float* W1         = (const float*)d_in[8];
    const float* b1         = (const float*)d_in[9];
    const float* W2         = (const float*)d_in[10];
    const float* b2         = (const float*)d_in[11];
    const float* W3         = (const float*)d_in[12];
    const float* b3         = (const float*)d_in[13];
    const float* Wr         = (const float*)d_in[14];
    const float* br         = (const float*)d_in[15];
    float*       out        = (float*)d_out;

    __nv_bfloat16 *Eb, *Wtb, *T, *W1b, *W2b, *W3b, *F0, *F1, *F2;
    cudaGetSymbolAddress((void**)&Eb,  g_Eb);
    cudaGetSymbolAddress((void**)&Wtb, g_Wtb);
    cudaGetSymbolAddress((void**)&T,   g_T);
    cudaGetSymbolAddress((void**)&W1b, g_W1b);
    cudaGetSymbolAddress((void**)&W2b, g_W2b);
    cudaGetSymbolAddress((void**)&W3b, g_W3b);
    cudaGetSymbolAddress((void**)&F0,  g_F0);
    cudaGetSymbolAddress((void**)&F1,  g_F1);
    cudaGetSymbolAddress((void**)&F2,  g_F2);

    const int SZ = 3072 + 1024 + 3 * 32768;   // 102400
    cudaFuncSetAttribute(gemm_tr, cudaFuncAttributeMaxDynamicSharedMemorySize, SZ);
    cudaFuncSetAttribute(gemm_bf<true, true, false>,  cudaFuncAttributeMaxDynamicSharedMemorySize, SZ);
    cudaFuncSetAttribute(gemm_bf<true, false, true>,  cudaFuncAttributeMaxDynamicSharedMemorySize, SZ);

    const dim3 blk(256);

    // 0) mark used entities + compact list                 [launches 1-3]
    zero_aux<<<147, blk>>>();
    mark_used<<<NB / 256, blk>>>(rows, cols);
    build_list<<<(NEMB + 255) / 256, blk>>>();

    // 1) fp32 -> bf16 conversions                          [launches 4-5]
    conv_emb<<<140625, blk>>>(user_inter, item_inter, Eb);
    conv_w<<<1572, blk>>>(Wt, W1, W2, W3, Wtb, W1b, W2b, W3b);

    // 2) Compacted transfer GEMM                           [launch 6 = ncu]
    gemm_tr<<<dim3(8, (NEMB + 127) / 128), blk, SZ>>>(Eb, Wtb, bt, T);

    // 3) Gather + elementwise product + concat
    build_factor<<<NB, blk>>>(rows, cols, uix, iix, T, F0);

    // 4) MLP layers; last fuses Wr-dot + br + 3.5
    gemm_bf<true, true, false><<<dim3(4, NB / 128), blk, SZ>>>(
        F0, W1b, b1, F1, nullptr, nullptr, NB, 512, 1024);
    gemm_bf<true, true, false><<<dim3(2, NB / 128), blk, SZ>>>(
        F1, W2b, b2, F2, nullptr, nullptr, NB, 256, 512);
    gemm_bf<true, false, true><<<dim3(1, NB / 128), blk, SZ>>>(
        F2, W3b, b3, out, Wr, br, NB, 128, 256);
}

// round 11
// speedup vs baseline: 1.4516x; 1.1114x over previous
#include <cuda_runtime.h>
#include <cuda_bf16.h>
#include <cstdint>
#include <cstddef>

// ===========================================================================
// DaConA on GB300 (sm_103 PTX target: mma.sync bf16 HMMA k16 + ldmatrix with
// hoisted swizzle addressing -- R8/R10 winner mainloop).
// R11: build_factor processes 8 batch elems/block (gather MLP 8x);
//      conv_emb converts only rows marked used (~80%).
// pred = MLP(concat(u_indep[r], i_indep[c], (Wt@u[r]+bt)*(Wt@i[c]+bt))) + 3.5
// ===========================================================================

#define NB      131072
#define NUSERS  100000
#define NITEMS  50000
#define NEMB    150000          // users then items
#define DIMC    960
#define DIMS    32
#define BF_E    8               // batch elems per build_factor block

__device__ __nv_bfloat16 g_Eb[(size_t)NEMB * DIMC];   // bf16 embeddings (u|i)
__device__ __nv_bfloat16 g_Wtb[(size_t)DIMC * DIMC];
__device__ __nv_bfloat16 g_T [(size_t)NEMB * DIMC];   // transfer outputs (u|i)
__device__ __nv_bfloat16 g_W1b[512 * 1024];
__device__ __nv_bfloat16 g_W2b[256 * 512];
__device__ __nv_bfloat16 g_W3b[128 * 256];
__device__ __nv_bfloat16 g_F0[(size_t)NB * 1024];
__device__ __nv_bfloat16 g_F1[(size_t)NB * 512];
__device__ __nv_bfloat16 g_F2[(size_t)NB * 256];
__device__ unsigned char g_used[NEMB];
__device__ int g_list[NEMB];
__device__ int g_cnt;

__device__ __forceinline__ uint32_t smem_u32(const void* p) {
    uint32_t a;
    asm("{ .reg .u64 t; cvta.to.shared.u64 t, %1; cvt.u32.u64 %0, t; }" : "=r"(a) : "l"(p));
    return a;
}
#define SWZ128(o) ((o) ^ (((o) >> 3) & 0x70))

__device__ __forceinline__ void cp16(uint32_t dst, const void* src, uint32_t sz) {
    asm volatile("cp.async.cg.shared.global [%0], [%1], 16, %2;" :: "r"(dst), "l"(src), "r"(sz));
}
__device__ __forceinline__ void ldsm4(uint32_t* r, uint32_t addr) {
    asm volatile("ldmatrix.sync.aligned.m8n8.x4.shared.b16 {%0,%1,%2,%3}, [%4];"
                 : "=r"(r[0]), "=r"(r[1]), "=r"(r[2]), "=r"(r[3]) : "r"(addr));
}
__device__ __forceinline__ void mma16(float* d, const uint32_t* a, const uint32_t* b) {
    asm volatile("mma.sync.aligned.m16n8k16.row.col.f32.bf16.bf16.f32 "
                 "{%0,%1,%2,%3}, {%4,%5,%6,%7}, {%8,%9}, {%0,%1,%2,%3};"
                 : "+f"(d[0]), "+f"(d[1]), "+f"(d[2]), "+f"(d[3])
                 : "r"(a[0]), "r"(a[1]), "r"(a[2]), "r"(a[3]), "r"(b[0]), "r"(b[1]));
}

// ---------------------------------------------------------------------------
// Aux: zero bitmap+counter; mark used entities; build compact list.
// ---------------------------------------------------------------------------
__global__ __launch_bounds__(256) void zero_aux() {
    const int i = blockIdx.x * 256 + threadIdx.x;
    if (i < NEMB / 4) ((uint32_t*)g_used)[i] = 0;
    if (i == 0) g_cnt = 0;
}
__global__ __launch_bounds__(256) void mark_used(
    const int* __restrict__ rows, const int* __restrict__ cols) {
    const int i = blockIdx.x * 256 + threadIdx.x;
    g_used[rows[i]] = 1;
    g_used[NUSERS + cols[i]] = 1;
}
__global__ __launch_bounds__(256) void build_list() {
    const int e = blockIdx.x * 256 + threadIdx.x;
    if (e < NEMB && g_used[e]) {
        int p = atomicAdd(&g_cnt, 1);
        g_list[p] = e;
    }
}

// ---------------------------------------------------------------------------
// fp32 -> bf16 embedding conversion, USED rows only. 2 rows per block,
// threads 0..239 active (960 floats = 240 float4 per row).
// ---------------------------------------------------------------------------
__global__ __launch_bounds__(256) void conv_emb(
    const float* __restrict__ user_inter, const float* __restrict__ item_inter,
    __nv_bfloat16* __restrict__ Eb)
{
    const int t = threadIdx.x;
    if (t >= 240) return;
    const int r0 = blockIdx.x * 2;
    const uchar2 u = *(const uchar2*)(g_used + r0);

    const float* s0 = (r0 < NUSERS) ? user_inter + (size_t)r0 * DIMC
                                    : item_inter + (size_t)(r0 - NUSERS) * DIMC;
    const int r1 = r0 + 1;
    const float* s1 = (r1 < NUSERS) ? user_inter + (size_t)r1 * DIMC
                                    : item_inter + (size_t)(r1 - NUSERS) * DIMC;
    float4 v0, v1;
    if (u.x) v0 = *(const float4*)(s0 + t * 4);
    if (u.y) v1 = *(const float4*)(s1 + t * 4);
    if (u.x) {
        __nv_bfloat16* d = Eb + (size_t)r0 * DIMC + t * 4;
        *(__nv_bfloat162*)(d)     = __nv_bfloat162(__float2bfloat16(v0.x), __float2bfloat16(v0.y));
        *(__nv_bfloat162*)(d + 2) = __nv_bfloat162(__float2bfloat16(v0.z), __float2bfloat16(v0.w));
    }
    if (u.y) {
        __nv_bfloat16* d = Eb + (size_t)r1 * DIMC + t * 4;
        *(__nv_bfloat162*)(d)     = __nv_bfloat162(__float2bfloat16(v1.x), __float2bfloat16(v1.y));
        *(__nv_bfloat162*)(d + 2) = __nv_bfloat162(__float2bfloat16(v1.z), __float2bfloat16(v1.w));
    }
}

// ---------------------------------------------------------------------------
// Wt(900) | W1(512) | W2(128) | W3(32) fp32 -> bf16, 1024 elems/block
// ---------------------------------------------------------------------------
__device__ __forceinline__ void conv_blk(const float* src, __nv_bfloat16* dst, size_t blk) {
    const size_t i = blk * 1024 + threadIdx.x * 4;
    float4 v = *(const float4*)(src + i);
    *(__nv_bfloat162*)(dst + i)     = __nv_bfloat162(__float2bfloat16(v.x), __float2bfloat16(v.y));
    *(__nv_bfloat162*)(dst + i + 2) = __nv_bfloat162(__float2bfloat16(v.z), __float2bfloat16(v.w));
}
__global__ __launch_bounds__(256) void conv_w(
    const float* __restrict__ Wt, const float* __restrict__ W1,
    const float* __restrict__ W2, const float* __restrict__ W3,
    __nv_bfloat16* __restrict__ Wtb, __nv_bfloat16* __restrict__ W1b,
    __nv_bfloat16* __restrict__ W2b, __nv_bfloat16* __restrict__ W3b)
{
    const int b = blockIdx.x;
    if      (b < 900)  conv_blk(Wt, Wtb, b);
    else if (b < 1412) conv_blk(W1, W1b, b - 900);
    else if (b < 1540) conv_blk(W2, W2b, b - 1412);
    else               conv_blk(W3, W3b, b - 1540);
}

// ---------------------------------------------------------------------------
// Transfer GEMM over COMPACTED rows (R10):
//   T[list[r]][n] = sum_k Eb[list[r]][k] * Wtb[n][k] + bt[n]
// ---------------------------------------------------------------------------
__global__ __launch_bounds__(256) void gemm_tr(
    const __nv_bfloat16* __restrict__ Eb, const __nv_bfloat16* __restrict__ Bw,
    const float* __restrict__ bias, __nv_bfloat16* __restrict__ T)
{
    const int cnt = g_cnt;
    const int bm = blockIdx.y * 128;
    if (bm >= cnt) return;
    const int bn = blockIdx.x * 128;

    extern __shared__ char smem[];
    const uint32_t base = smem_u32(smem);
    const int t = threadIdx.x;
    const int wid = t >> 5, lane = t & 31;
    const int wm = wid >> 2, wn = wid & 3;
    const int g = lane >> 2, q = lane & 3;

    constexpr int TILE = 16384;
    constexpr int SB   = 2 * TILE;

    float* biass = (float*)(smem);
    int*   idxs  = (int*)(smem + 1024);
    const uint32_t tiles = (base + 3072 + 1023) & ~1023u;

    for (int j = t; j < 128; j += 256) {
        int gn = bn + j;
        biass[j] = (gn < DIMC) ? bias[gn] : 0.f;
        idxs[j]  = (bm + j < cnt) ? g_list[bm + j] : 0;
    }

    const int seg = t & 7;
    const int rb  = t >> 3;

    int aidx[4]; uint32_t aok[4];
#pragma unroll
    for (int rr = 0; rr < 4; rr++) {
        int gr = bm + rb + rr * 32;
        aok[rr]  = (gr < cnt) ? 16u : 0u;
        aidx[rr] = (gr < cnt) ? g_list[gr] : 0;
    }

    auto load_chunk = [&](int c, int s) {
        const uint32_t at = tiles + s * SB;
        const uint32_t bt_ = at + TILE;
#pragma unroll
        for (int rr = 0; rr < 4; rr++) {
            int row = rb + rr * 32;
            const __nv_bfloat16* src = Eb + (size_t)aidx[rr] * DIMC + c * 64 + seg * 8;
            cp16(at + SWZ128(row * 128 + seg * 16), src, aok[rr]);
        }
#pragma unroll
        for (int rr = 0; rr < 4; rr++) {
            int row = rb + rr * 32;
            int gn  = bn + row;
            int ok  = gn < DIMC;
            const __nv_bfloat16* src = Bw + (size_t)(ok ? gn : 0) * DIMC + c * 64 + seg * 8;
            cp16(bt_ + SWZ128(row * 128 + seg * 16), src, ok ? 16u : 0u);
        }
        asm volatile("cp.async.commit_group;" ::: "memory");
    };

    float acc[4][4][4];
#pragma unroll
    for (int i = 0; i < 4; i++)
#pragma unroll
        for (int j = 0; j < 4; j++)
#pragma unroll
            for (int v = 0; v < 4; v++) acc[i][j][v] = 0.f;

    const int arow = lane & 15;
    const int aoff = (lane >> 4) * 16;
    const int axor = (arow & 7) << 4;
    const int bm8  = lane >> 3;
    const int brow = ((bm8 >> 1) << 3) + (lane & 7);
    const int boff = (bm8 & 1) * 16;
    const int bxor = (lane & 7) << 4;
    uint32_t off_a[4], off_b[4];
#pragma unroll
    for (int ks = 0; ks < 4; ks++) {
        off_a[ks] = (uint32_t)((wm * 64 + arow) * 128 + ((ks * 32 + aoff) ^ axor));
        off_b[ks] = (uint32_t)((wn * 32 + brow) * 128 + ((ks * 32 + boff) ^ bxor)) + TILE;
    }

    const int NKc = DIMC >> 6;          // 15 chunks
    load_chunk(0, 0);
    load_chunk(1, 1);

    for (int i = 0; i < NKc; i++) {
        const int s = i - (i / 3) * 3;
        if (i + 1 < NKc) asm volatile("cp.async.wait_group 1;" ::: "memory");
        else             asm volatile("cp.async.wait_group 0;" ::: "memory");
        __syncthreads();
        if (i + 2 < NKc) {
            int s2 = i + 2; s2 -= (s2 / 3) * 3;
            load_chunk(i + 2, s2);
        }

        const uint32_t st = tiles + s * SB;
#pragma unroll
        for (int ks = 0; ks < 4; ks++) {
            uint32_t af[4][4], bf[4][2];
            const uint32_t ab = st + off_a[ks];
            const uint32_t bb = st + off_b[ks];
#pragma unroll
            for (int mt = 0; mt < 4; mt++)
                ldsm4(af[mt], ab + mt * 2048);
#pragma unroll
            for (int np = 0; np < 2; np++) {
                uint32_t r[4];
                ldsm4(r, bb + np * 2048);
                bf[2 * np][0] = r[0]; bf[2 * np][1] = r[1];
                bf[2 * np + 1][0] = r[2]; bf[2 * np + 1][1] = r[3];
            }
#pragma unroll
            for (int mt = 0; mt < 4; mt++)
#pragma unroll
                for (int nt = 0; nt < 4; nt++)
                    mma16(acc[mt][nt], af[mt], bf[nt]);
        }
    }
    __syncthreads();

#pragma unroll
    for (int mt = 0; mt < 4; mt++) {
        const int er0 = wm * 64 + mt * 16 + g;
#pragma unroll
        for (int nt = 0; nt < 4; nt++) {
            const int jc = wn * 32 + nt * 8 + 2 * q;
            const int gn = bn + jc;
            if (gn >= DIMC) continue;
            const float bx = biass[jc], by = biass[jc + 1];
            float x0 = acc[mt][nt][0] + bx, x1 = acc[mt][nt][1] + by;
            float x2 = acc[mt][nt][2] + bx, x3 = acc[mt][nt][3] + by;
            if (bm + er0 < cnt)
                *(__nv_bfloat162*)(T + (size_t)idxs[er0] * DIMC + gn) =
                    __nv_bfloat162(__float2bfloat16(x0), __float2bfloat16(x1));
            if (bm + er0 + 8 < cnt)
                *(__nv_bfloat162*)(T + (size_t)idxs[er0 + 8] * DIMC + gn) =
                    __nv_bfloat162(__float2bfloat16(x2), __float2bfloat16(x3));
        }
    }
}

// ---------------------------------------------------------------------------
// bf16 mma.sync NT GEMM (R8 winner): BM=BN=128, 3-stage, ldmatrix hoisted.
// FINAL: fuse out[b] = tanh(row) . Wr + br + 3.5 (requires N == 128).
// ---------------------------------------------------------------------------
template<bool TANH, bool OUT_BF16, bool FINAL>
__global__ __launch_bounds__(256) void gemm_bf(
    const __nv_bfloat16* __restrict__ A, const __nv_bfloat16* __restrict__ Bw,
    const float* __restrict__ bias, void* __restrict__ Cv,
    const float* __restrict__ Wr, const float* __restrict__ brp,
    int M, int N, int K)
{
    extern __shared__ char smem[];
    const uint32_t base = smem_u32(smem);
    const int t = threadIdx.x;
    const int wid = t >> 5, lane = t & 31;
    const int wm = wid >> 2, wn = wid & 3;
    const int g = lane >> 2, q = lane & 3;

    constexpr int TILE = 16384;
    constexpr int SB   = 2 * TILE;
    const int bm = blockIdx.y * 128;
    const int bn = blockIdx.x * 128;

    float* biass = (float*)(smem);
    float* wrs   = (float*)(smem + 512);
    float* part  = (float*)(smem + 1024);
    const uint32_t tiles = (base + 3072 + 1023) & ~1023u;

    for (int j = t; j < 128; j += 256) {
        int gn = bn + j;
        biass[j] = (gn < N) ? bias[gn] : 0.f;
        if (FINAL) wrs[j] = Wr[j];
    }

    const int seg = t & 7;
    const int rb  = t >> 3;

    auto load_chunk = [&](int c, int s) {
        const uint32_t at = tiles + s * SB;
        const uint32_t bt_ = at + TILE;
#pragma unroll
        for (int rr = 0; rr < 4; rr++) {
            int row = rb + rr * 32;
            int gr  = bm + row;
            int ok  = gr < M;
            const __nv_bfloat16* src = A + (size_t)(ok ? gr : 0) * K + c * 64 + seg * 8;
            cp16(at + SWZ128(row * 128 + seg * 16), src, ok ? 16u : 0u);
        }
#pragma unroll
        for (int rr = 0; rr < 4; rr++) {
            int row = rb + rr * 32;
            int gn  = bn + row;
            int ok  = gn < N;
            const __nv_bfloat16* src = Bw + (size_t)(ok ? gn : 0) * K + c * 64 + seg * 8;
            cp16(bt_ + SWZ128(row * 128 + seg * 16), src, ok ? 16u : 0u);
        }
        asm volatile("cp.async.commit_group;" ::: "memory");
    };

    float acc[4][4][4];
#pragma unroll
    for (int i = 0; i < 4; i++)
#pragma unroll
        for (int j = 0; j < 4; j++)
#pragma unroll
            for (int v = 0; v < 4; v++) acc[i][j][v] = 0.f;

    const int arow = lane & 15;
    const int aoff = (lane >> 4) * 16;
    const int axor = (arow & 7) << 4;
    const int bm8  = lane >> 3;
    const int brow = ((bm8 >> 1) << 3) + (lane & 7);
    const int boff = (bm8 & 1) * 16;
    const int bxor = (lane & 7) << 4;
    uint32_t off_a[4], off_b[4];
#pragma unroll
    for (int ks = 0; ks < 4; ks++) {
        off_a[ks] = (uint32_t)((wm * 64 + arow) * 128 + ((ks * 32 + aoff) ^ axor));
        off_b[ks] = (uint32_t)((wn * 32 + brow) * 128 + ((ks * 32 + boff) ^ bxor)) + TILE;
    }

    const int NKc = K >> 6;
    load_chunk(0, 0);
    load_chunk(1, 1);

    for (int i = 0; i < NKc; i++) {
        const int s = i - (i / 3) * 3;
        if (i + 1 < NKc) asm volatile("cp.async.wait_group 1;" ::: "memory");
        else             asm volatile("cp.async.wait_group 0;" ::: "memory");
        __syncthreads();
        if (i + 2 < NKc) {
            int s2 = i + 2; s2 -= (s2 / 3) * 3;
            load_chunk(i + 2, s2);
        }

        const uint32_t st = tiles + s * SB;
#pragma unroll
        for (int ks = 0; ks < 4; ks++) {
            uint32_t af[4][4], bf[4][2];
            const uint32_t ab = st + off_a[ks];
            const uint32_t bb = st + off_b[ks];
#pragma unroll
            for (int mt = 0; mt < 4; mt++)
                ldsm4(af[mt], ab + mt * 2048);
#pragma unroll
            for (int np = 0; np < 2; np++) {
                uint32_t r[4];
                ldsm4(r, bb + np * 2048);
                bf[2 * np][0] = r[0]; bf[2 * np][1] = r[1];
                bf[2 * np + 1][0] = r[2]; bf[2 * np + 1][1] = r[3];
            }
#pragma unroll
            for (int mt = 0; mt < 4; mt++)
#pragma unroll
                for (int nt = 0; nt < 4; nt++)
                    mma16(acc[mt][nt], af[mt], bf[nt]);
        }
    }
    __syncthreads();

    if (FINAL) {
#pragma unroll
        for (int mt = 0; mt < 4; mt++) {
            float p0 = 0.f, p1 = 0.f;
#pragma unroll
            for (int nt = 0; nt < 4; nt++) {
                const int jc = wn * 32 + nt * 8 + 2 * q;
                const float bx = biass[jc], by = biass[jc + 1];
                const float wx = wrs[jc],  wy = wrs[jc + 1];
                p0 += tanhf(acc[mt][nt][0] + bx) * wx + tanhf(acc[mt][nt][1] + by) * wy;
                p1 += tanhf(acc[mt][nt][2] + bx) * wx + tanhf(acc[mt][nt][3] + by) * wy;
            }
            p0 += __shfl_xor_sync(0xFFFFFFFFu, p0, 1);
            p0 += __shfl_xor_sync(0xFFFFFFFFu, p0, 2);
            p1 += __shfl_xor_sync(0xFFFFFFFFu, p1, 1);
            p1 += __shfl_xor_sync(0xFFFFFFFFu, p1, 2);
            if (q == 0) {
                part[(wm * 64 + mt * 16 + g) * 4 + wn]     = p0;
                part[(wm * 64 + mt * 16 + g + 8) * 4 + wn] = p1;
            }
        }
        __syncthreads();
        if (t < 128) {
            float s = part[t * 4] + part[t * 4 + 1] + part[t * 4 + 2] + part[t * 4 + 3];
            if (bm + t < M) ((float*)Cv)[bm + t] = s + brp[0] + 3.5f;
        }
        return;
    }

#pragma unroll
    for (int mt = 0; mt < 4; mt++) {
        const int r0 = bm + wm * 64 + mt * 16 + g;
#pragma unroll
        for (int nt = 0; nt < 4; nt++) {
            const int jc = wn * 32 + nt * 8 + 2 * q;
            const int gn = bn + jc;
            if (gn >= N) continue;
            const float bx = biass[jc], by = biass[jc + 1];
            float x0 = acc[mt][nt][0] + bx, x1 = acc[mt][nt][1] + by;
            float x2 = acc[mt][nt][2] + bx, x3 = acc[mt][nt][3] + by;
            if (TANH) { x0 = tanhf(x0); x1 = tanhf(x1); x2 = tanhf(x2); x3 = tanhf(x3); }
            if (OUT_BF16) {
                __nv_bfloat16* C = (__nv_bfloat16*)Cv;
                if (r0 < M)
                    *(__nv_bfloat162*)(C + (size_t)r0 * N + gn) =
                        __nv_bfloat162(__float2bfloat16(x0), __float2bfloat16(x1));
                if (r0 + 8 < M)
                    *(__nv_bfloat162*)(C + (size_t)(r0 + 8) * N + gn) =
                        __nv_bfloat162(__float2bfloat16(x2), __float2bfloat16(x3));
            } else {
                float* C = (float*)Cv;
                if (r0 < M)     *(float2*)(C + (size_t)r0 * N + gn)       = make_float2(x0, x1);
                if (r0 + 8 < M) *(float2*)(C + (size_t)(r0 + 8) * N + gn) = make_float2(x2, x3);
            }
        }
    }
}

// ---------------------------------------------------------------------------
// Gather + elementwise product + concat into F0[B, 1024] (bf16).
// BF_E batch elements per block; all gathers issued before consumption.
// ---------------------------------------------------------------------------
__global__ __launch_bounds__(256) void build_factor(
    const int* __restrict__ rows, const int* __restrict__ cols,
    const float* __restrict__ uix, const float* __restrict__ iix,
    const __nv_bfloat16* __restrict__ T, __nv_bfloat16* __restrict__ F0)
{
    const int b0 = blockIdx.x * BF_E;
    const int t  = threadIdx.x;
    const int f  = t * 4;

    int rr[BF_E], cc[BF_E];
    {
        int4 ra = *(const int4*)(rows + b0);
        int4 rb_ = *(const int4*)(rows + b0 + 4);
        int4 ca = *(const int4*)(cols + b0);
        int4 cb = *(const int4*)(cols + b0 + 4);
        rr[0] = ra.x; rr[1] = ra.y; rr[2] = ra.z; rr[3] = ra.w;
        rr[4] = rb_.x; rr[5] = rb_.y; rr[6] = rb_.z; rr[7] = rb_.w;
        cc[0] = ca.x; cc[1] = ca.y; cc[2] = ca.z; cc[3] = ca.w;
        cc[4] = cb.x; cc[5] = cb.y; cc[6] = cb.z; cc[7] = cb.w;
    }

    if (f < 32) {
        float4 v[BF_E];
#pragma unroll
        for (int e = 0; e < BF_E; e++)
            v[e] = *(const float4*)(uix + (size_t)rr[e] * DIMS + f);
#pragma unroll
        for (int e = 0; e < BF_E; e++) {
            __nv_bfloat16* o = F0 + (size_t)(b0 + e) * 1024 + f;
            *(__nv_bfloat162*)(o)     = __nv_bfloat162(__float2bfloat16(v[e].x), __float2bfloat16(v[e].y));
            *(__nv_bfloat162*)(o + 2) = __nv_bfloat162(__float2bfloat16(v[e].z), __float2bfloat16(v[e].w));
        }
    } else if (f < 64) {
        float4 v[BF_E];
#pragma unroll
        for (int e = 0; e < BF_E; e++)
            v[e] = *(const float4*)(iix + (size_t)cc[e] * DIMS + (f - 32));
#pragma unroll
        for (int e = 0; e < BF_E; e++) {
            __nv_bfloat16* o = F0 + (size_t)(b0 + e) * 1024 + f;
            *(__nv_bfloat162*)(o)     = __nv_bfloat162(__float2bfloat16(v[e].x), __float2bfloat16(v[e].y));
            *(__nv_bfloat162*)(o + 2) = __nv_bfloat162(__float2bfloat16(v[e].z), __float2bfloat16(v[e].w));
        }
    } else {
        uint2 av[BF_E], bv[BF_E];
#pragma unroll
        for (int e = 0; e < BF_E; e++)
            av[e] = *(const uint2*)(T + (size_t)rr[e] * DIMC + (f - 64));
#pragma unroll
        for (int e = 0; e < BF_E; e++)
            bv[e] = *(const uint2*)(T + (size_t)(NUSERS + cc[e]) * DIMC + (f - 64));
#pragma unroll
        for (int e = 0; e < BF_E; e++) {
            __nv_bfloat162 a0 = *(__nv_bfloat162*)&av[e].x;
            __nv_bfloat162 a1 = *(__nv_bfloat162*)&av[e].y;
            __nv_bfloat162 b0_ = *(__nv_bfloat162*)&bv[e].x;
            __nv_bfloat162 b1_ = *(__nv_bfloat162*)&bv[e].y;
            __nv_bfloat162 p0 = __hmul2(a0, b0_);
            __nv_bfloat162 p1 = __hmul2(a1, b1_);
            uint2 w;
            w.x = *(uint32_t*)&p0;
            w.y = *(uint32_t*)&p1;
            *(uint2*)(F0 + (size_t)(b0 + e) * 1024 + f) = w;
        }
    }
}

// ---------------------------------------------------------------------------
extern "C" void kernel_launch(void* const* d_in, const int* in_sizes, int n_in,
                              void* d_out, int out_size)
{
    const int*   rows       = (const int*)d_in[0];
    const int*   cols       = (const int*)d_in[1];
    const float* user_inter = (const float*)d_in[2];
    const float* item_inter = (const float*)d_in[3];
    const float* uix        = (const float*)d_in[4];
    const float* iix        = (const float*)d_in[5];
    const float* Wt         = (const float*)d_in[6];
    const float* bt         = (const float*)d_in[7];
    const float* W1         = (const float*)d_in[8];
    const float* b1         = (const float*)d_in[9];
    const float* W2         = (const float*)d_in[10];
    const float* b2         = (const float*)d_in[11];
    const float* W3         = (const float*)d_in[12];
    const float* b3         = (const float*)d_in[13];
    const float* Wr         = (const float*)d_in[14];
    const float* br         = (const float*)d_in[15];
    float*       out        = (float*)d_out;

    __nv_bfloat16 *Eb, *Wtb, *T, *W1b, *W2b, *W3b, *F0, *F1, *F2;
    cudaGetSymbolAddress((void**)&Eb,  g_Eb);
    cudaGetSymbolAddress((void**)&Wtb, g_Wtb);
    cudaGetSymbolAddress((void**)&T,   g_T);
    cudaGetSymbolAddress((void**)&W1b, g_W1b);
    cudaGetSymbolAddress((void**)&W2b, g_W2b);
    cudaGetSymbolAddress((void**)&W3b, g_W3b);
    cudaGetSymbolAddress((void**)&F0,  g_F0);
    cudaGetSymbolAddress((void**)&F1,  g_F1);
    cudaGetSymbolAddress((void**)&F2,  g_F2);

    const int SZ = 3072 + 1024 + 3 * 32768;   // 102400
    cudaFuncSetAttribute(gemm_tr, cudaFuncAttributeMaxDynamicSharedMemorySize, SZ);
    cudaFuncSetAttribute(gemm_bf<true, true, false>,  cudaFuncAttributeMaxDynamicSharedMemorySize, SZ);
    cudaFuncSetAttribute(gemm_bf<true, false, true>,  cudaFuncAttributeMaxDynamicSharedMemorySize, SZ);

    const dim3 blk(256);

    // 0) mark used entities + compact list                 [launches 1-3]
    zero_aux<<<147, blk>>>();
    mark_used<<<NB / 256, blk>>>(rows, cols);
    build_list<<<(NEMB + 255) / 256, blk>>>();

    // 1) fp32 -> bf16 conversions (used rows only)         [launches 4-5]
    conv_emb<<<NEMB / 2, blk>>>(user_inter, item_inter, Eb);
    conv_w<<<1572, blk>>>(Wt, W1, W2, W3, Wtb, W1b, W2b, W3b);

    // 2) Compacted transfer GEMM                           [launch 6 = ncu]
    gemm_tr<<<dim3(8, (NEMB + 127) / 128), blk, SZ>>>(Eb, Wtb, bt, T);

    // 3) Gather + elementwise product + concat
    build_factor<<<NB / BF_E, blk>>>(rows, cols, uix, iix, T, F0);

    // 4) MLP layers; last fuses Wr-dot + br + 3.5
    gemm_bf<true, true, false><<<dim3(4, NB / 128), blk, SZ>>>(
        F0, W1b, b1, F1, nullptr, nullptr, NB, 512, 1024);
    gemm_bf<true, true, false><<<dim3(2, NB / 128), blk, SZ>>>(
        F1, W2b, b2, F2, nullptr, nullptr, NB, 256, 512);
    gemm_bf<true, false, true><<<dim3(1, NB / 128), blk, SZ>>>(
        F2, W3b, b3, out, Wr, br, NB, 128, 256);
}